// round 13
// baseline (speedup 1.0000x reference)
#include <cuda_runtime.h>
#include <cuda_bf16.h>
#include <cstdint>

typedef unsigned long long u64;

#define BB 4
#define NN 4096
#define MM 4096
#define MT 64             // threads per block (2 warps)
#define MPT 4             // m's per thread
#define MTILE (MT * MPT)  // 256 m's per tile
#define MTILES (MM / MTILE)   // 16
#define NT 256            // n's per chunk
#define NQ (NT / 2)       // packed pairs per chunk = 128
#define NCHUNK (NN / NT)  // 16
#define RED_BLOCKS 64
#define RED_T 256

#define EPSF     1e-8f
#define INV_LN2  1.4426950408889634f
// 1.5 * ln(2*3.14159)  (reference uses pi = 3.14159)
#define C_OFF    2.7568143383208773f

// transposed partials: g_part[m_global][ch] -- 16 contiguous floats per m
__device__ float g_part[BB * MM][NCHUNK];
__device__ float g_red[RED_BLOCKS];
__device__ unsigned g_count = 0;

// ---------------- packed f32x2 primitives ----------------
#define FMA2(d, a, b, c) asm("fma.rn.f32x2 %0, %1, %2, %3;"  : "=l"(d) : "l"(a), "l"(b), "l"(c))
#define ADD2(d, a, b)    asm("add.rn.f32x2 %0, %1, %2;"      : "=l"(d) : "l"(a), "l"(b))

__device__ __forceinline__ u64 pk(float lo, float hi) {
    u64 r;
    asm("mov.b64 %0, {%1, %2};" : "=l"(r) : "f"(lo), "f"(hi));
    return r;
}

__device__ __forceinline__ float ex2f(float x) {
    float r;
    asm("ex2.approx.f32 %0, %1;" : "=f"(r) : "f"(x));
    return r;
}

__device__ __forceinline__ float warp_sum(float v) {
#pragma unroll
    for (int o = 16; o > 0; o >>= 1)
        v += __shfl_xor_sync(0xFFFFFFFFu, v, o);
    return v;
}

// -------- main: fused prep + partial sums, 4 m's per thread ----------------
__global__ __launch_bounds__(MT) void gmm_main_kernel(const float* __restrict__ xyz,
                                                      const float* __restrict__ sig,
                                                      const float* __restrict__ target) {
    // per-q packed coefficient pairs: D12={cp,apx} D34={apy,bpz} D56={na,nb}
    __shared__ ulonglong2 sD12[NQ], sD34[NQ], sD56[NQ];

    const int mt = blockIdx.x;     // 0..MTILES-1
    const int ch = blockIdx.y;     // 0..NCHUNK-1
    const int b  = blockIdx.z;     // 0..BB-1
    const int tid = threadIdx.x;

    // ---- in-block prep: NT=256 n's with 64 threads (4 each) ----
    for (int jj = tid; jj < NT; jj += MT) {
        const int n = b * NN + ch * NT + jj;
        float px = xyz[3 * n + 0], py = xyz[3 * n + 1], pz = xyz[3 * n + 2];
        float sxy = sig[2 * n + 0] + EPSF;
        float sz  = sig[2 * n + 1] + EPSF;
        float a  = __fdividef(0.5f * INV_LN2, sxy);   // log2-domain coefs
        float bz = __fdividef(0.5f * INV_LN2, sz);
        float c  = (-__logf(sxy) - 0.5f * __logf(sz) - C_OFF) * INV_LN2;
        float cp  = c - a * (px * px + py * py) - bz * (pz * pz);
        float apx = 2.0f * a * px;
        float apy = 2.0f * a * py;
        float bpz = 2.0f * bz * pz;

        const int q = jj >> 1, par = jj & 1;
        float* f12 = (float*)sD12;       // lanes: [4q+0/1]=cp_{e,o} [4q+2/3]=apx_{e,o}
        float* f34 = (float*)sD34;
        float* f56 = (float*)sD56;
        f12[4 * q + 0 + par] = cp;
        f12[4 * q + 2 + par] = apx;
        f34[4 * q + 0 + par] = apy;
        f34[4 * q + 2 + par] = bpz;
        f56[4 * q + 0 + par] = -a;
        f56[4 * q + 2 + par] = -bz;
    }

    // ---- per-m values: four m's, 64 apart ----
    u64 TX[MPT], TY[MPT], TZ[MPT], ST[MPT], TZ2[MPT];
    int mbase = mt * MTILE + tid;
#pragma unroll
    for (int k = 0; k < MPT; k++) {
        const int m = mbase + k * MT;
        const float* tp = target + ((size_t)b * MM + m) * 3;
        float tx = tp[0], ty = tp[1], tz = tp[2];
        TX[k]  = pk(tx, tx);
        TY[k]  = pk(ty, ty);
        TZ[k]  = pk(tz, tz);
        ST[k]  = pk(tx * tx + ty * ty, tx * tx + ty * ty);
        TZ2[k] = pk(tz * tz, tz * tz);
    }

    __syncthreads();

    u64 acc[MPT];
#pragma unroll
    for (int k = 0; k < MPT; k++) acc[k] = 0ull;

#pragma unroll 2
    for (int j = 0; j < NQ; j++) {
        ulonglong2 D12 = sD12[j], D34 = sD34[j], D56 = sD56[j];
        u64 x[MPT];

        // four independent 5-FMA2 chains (ILP)
#pragma unroll
        for (int k = 0; k < MPT; k++) { FMA2(x[k], D12.y, TX[k], D12.x); }
#pragma unroll
        for (int k = 0; k < MPT; k++) { FMA2(x[k], D34.x, TY[k], x[k]); }
#pragma unroll
        for (int k = 0; k < MPT; k++) { FMA2(x[k], D34.y, TZ[k], x[k]); }
#pragma unroll
        for (int k = 0; k < MPT; k++) { FMA2(x[k], D56.x, ST[k], x[k]); }
#pragma unroll
        for (int k = 0; k < MPT; k++) { FMA2(x[k], D56.y, TZ2[k], x[k]); }

#pragma unroll
        for (int k = 0; k < MPT; k++) {
            float lo, hi;
            asm("mov.b64 {%0, %1}, %2;" : "=f"(lo), "=f"(hi) : "l"(x[k]));
            // MUFU pipe: exp2; flushes huge-negative to 0 natively
            float e0 = ex2f(lo);
            float e1 = ex2f(hi);
            u64 pe = pk(e0, e1);
            ADD2(acc[k], pe, acc[k]);
        }
    }

#pragma unroll
    for (int k = 0; k < MPT; k++) {
        float v0 = __uint_as_float((unsigned)acc[k]);
        float v1 = __uint_as_float((unsigned)(acc[k] >> 32));
        g_part[b * MM + mbase + k * MT][ch] = v0 + v1;
    }
}

// ---------- reduction: 64 blocks x 256 thr; shuffle-based, 1 barrier -------
__global__ __launch_bounds__(RED_T) void gmm_red_kernel(float* __restrict__ out) {
    __shared__ float wsum[RED_T / 32];    // 8 per-warp sums
    __shared__ bool amLast;
    const int tid  = threadIdx.x;
    const int lane = tid & 31;
    const int wid  = tid >> 5;
    const int i = blockIdx.x * RED_T + tid;     // 0 .. BB*MM-1

    // 16 contiguous floats per m: 4 x LDG.128, MLP=4
    const float4* p = (const float4*)g_part[i];
    float4 v0 = p[0], v1 = p[1], v2 = p[2], v3 = p[3];
    float s = ((v0.x + v0.y) + (v0.z + v0.w))
            + ((v1.x + v1.y) + (v1.z + v1.w))
            + ((v2.x + v2.y) + (v2.z + v2.w))
            + ((v3.x + v3.y) + (v3.z + v3.w));
    float nll = -__logf(s);                     // nll = -ln(sum e^lp)

    float w = warp_sum(nll);                    // 5 shfl, no barriers
    if (lane == 0) wsum[wid] = w;
    __syncthreads();                            // the only block barrier

    if (wid == 0) {
        float v = (lane < RED_T / 32) ? wsum[lane] : 0.0f;
#pragma unroll
        for (int o = 4; o > 0; o >>= 1)
            v += __shfl_xor_sync(0xFFFFFFFFu, v, o);
        if (lane == 0) {
            g_red[blockIdx.x] = v;
            __threadfence();
            amLast = (atomicAdd(&g_count, 1u) == RED_BLOCKS - 1);
        }
    }
    __syncthreads();
    if (!amLast) return;

    // final: one warp combines 64 block sums (fixed tree order, deterministic)
    if (wid == 0) {
        float v = g_red[lane] + g_red[lane + 32];
#pragma unroll
        for (int o = 16; o > 0; o >>= 1)
            v += __shfl_xor_sync(0xFFFFFFFFu, v, o);
        if (lane == 0) {
            out[0] = v * (1.0f / (BB * MM));
            g_count = 0;                        // reset for next graph replay
        }
    }
}

extern "C" void kernel_launch(void* const* d_in, const int* in_sizes, int n_in,
                              void* d_out, int out_size) {
    const float* pred_xyz   = (const float*)d_in[0];  // [B, N, 3]
    const float* pred_sigma = (const float*)d_in[1];  // [B, N, 2]
    const float* target     = (const float*)d_in[2];  // [B, M, 3]
    float* out = (float*)d_out;

    dim3 grid(MTILES, NCHUNK, BB);
    gmm_main_kernel<<<grid, MT>>>(pred_xyz, pred_sigma, target);

    gmm_red_kernel<<<RED_BLOCKS, RED_T>>>(out);
}

// round 15
// speedup vs baseline: 1.1325x; 1.1325x over previous
#include <cuda_runtime.h>
#include <cuda_bf16.h>
#include <cstdint>

typedef unsigned long long u64;

#define BB 4
#define NN 4096
#define MM 4096
#define MT 128            // threads per block (4 warps -- feeds all SMSPs)
#define MPT 4             // m's per thread
#define MTILE (MT * MPT)  // 512 m's per tile
#define MTILES (MM / MTILE)   // 8
#define NT 128            // n's per chunk
#define NQ (NT / 2)       // packed pairs per chunk = 64
#define NCHUNK (NN / NT)  // 32
#define RED_BLOCKS 64
#define RED_T 256

#define EPSF     1e-8f
#define INV_LN2  1.4426950408889634f
// 1.5 * ln(2*3.14159)  (reference uses pi = 3.14159)
#define C_OFF    2.7568143383208773f

// transposed partials: g_part[m_global][ch] -- 32 contiguous floats per m
__device__ float g_part[BB * MM][NCHUNK];
__device__ float g_red[RED_BLOCKS];
__device__ unsigned g_count = 0;

// ---------------- packed f32x2 primitives ----------------
#define FMA2(d, a, b, c) asm("fma.rn.f32x2 %0, %1, %2, %3;"  : "=l"(d) : "l"(a), "l"(b), "l"(c))
#define ADD2(d, a, b)    asm("add.rn.f32x2 %0, %1, %2;"      : "=l"(d) : "l"(a), "l"(b))

__device__ __forceinline__ u64 pk(float lo, float hi) {
    u64 r;
    asm("mov.b64 %0, {%1, %2};" : "=l"(r) : "f"(lo), "f"(hi));
    return r;
}

__device__ __forceinline__ float ex2f(float x) {
    float r;
    asm("ex2.approx.f32 %0, %1;" : "=f"(r) : "f"(x));
    return r;
}

__device__ __forceinline__ float warp_sum(float v) {
#pragma unroll
    for (int o = 16; o > 0; o >>= 1)
        v += __shfl_xor_sync(0xFFFFFFFFu, v, o);
    return v;
}

// -------- main: fused prep + partial sums, 4 m's per thread ----------------
__global__ __launch_bounds__(MT) void gmm_main_kernel(const float* __restrict__ xyz,
                                                      const float* __restrict__ sig,
                                                      const float* __restrict__ target) {
    // per-q packed coefficient pairs: D12={cp,apx} D34={apy,bpz} D56={na,nb}
    __shared__ ulonglong2 sD12[NQ], sD34[NQ], sD56[NQ];

    const int mt = blockIdx.x;     // 0..MTILES-1
    const int ch = blockIdx.y;     // 0..NCHUNK-1
    const int b  = blockIdx.z;     // 0..BB-1
    const int tid = threadIdx.x;

    // ---- in-block prep: NT=128 n's with 128 threads (1 each) ----
    {
        const int n = b * NN + ch * NT + tid;
        float px = xyz[3 * n + 0], py = xyz[3 * n + 1], pz = xyz[3 * n + 2];
        float sxy = sig[2 * n + 0] + EPSF;
        float sz  = sig[2 * n + 1] + EPSF;
        float a  = __fdividef(0.5f * INV_LN2, sxy);   // log2-domain coefs
        float bz = __fdividef(0.5f * INV_LN2, sz);
        float c  = (-__logf(sxy) - 0.5f * __logf(sz) - C_OFF) * INV_LN2;
        float cp  = c - a * (px * px + py * py) - bz * (pz * pz);
        float apx = 2.0f * a * px;
        float apy = 2.0f * a * py;
        float bpz = 2.0f * bz * pz;

        const int q = tid >> 1, par = tid & 1;
        float* f12 = (float*)sD12;       // lanes: [4q+0/1]=cp_{e,o} [4q+2/3]=apx_{e,o}
        float* f34 = (float*)sD34;
        float* f56 = (float*)sD56;
        f12[4 * q + 0 + par] = cp;
        f12[4 * q + 2 + par] = apx;
        f34[4 * q + 0 + par] = apy;
        f34[4 * q + 2 + par] = bpz;
        f56[4 * q + 0 + par] = -a;
        f56[4 * q + 2 + par] = -bz;
    }

    // ---- per-m values: four m's, 128 apart ----
    u64 TX[MPT], TY[MPT], TZ[MPT], ST[MPT], TZ2[MPT];
    const int mbase = mt * MTILE + tid;
#pragma unroll
    for (int k = 0; k < MPT; k++) {
        const int m = mbase + k * MT;
        const float* tp = target + ((size_t)b * MM + m) * 3;
        float tx = tp[0], ty = tp[1], tz = tp[2];
        TX[k]  = pk(tx, tx);
        TY[k]  = pk(ty, ty);
        TZ[k]  = pk(tz, tz);
        ST[k]  = pk(tx * tx + ty * ty, tx * tx + ty * ty);
        TZ2[k] = pk(tz * tz, tz * tz);
    }

    __syncthreads();

    u64 acc[MPT];
#pragma unroll
    for (int k = 0; k < MPT; k++) acc[k] = 0ull;

#pragma unroll 2
    for (int j = 0; j < NQ; j++) {
        ulonglong2 D12 = sD12[j], D34 = sD34[j], D56 = sD56[j];
        u64 x[MPT];

        // four independent 5-FMA2 chains (ILP)
#pragma unroll
        for (int k = 0; k < MPT; k++) { FMA2(x[k], D12.y, TX[k], D12.x); }
#pragma unroll
        for (int k = 0; k < MPT; k++) { FMA2(x[k], D34.x, TY[k], x[k]); }
#pragma unroll
        for (int k = 0; k < MPT; k++) { FMA2(x[k], D34.y, TZ[k], x[k]); }
#pragma unroll
        for (int k = 0; k < MPT; k++) { FMA2(x[k], D56.x, ST[k], x[k]); }
#pragma unroll
        for (int k = 0; k < MPT; k++) { FMA2(x[k], D56.y, TZ2[k], x[k]); }

#pragma unroll
        for (int k = 0; k < MPT; k++) {
            float lo, hi;
            asm("mov.b64 {%0, %1}, %2;" : "=f"(lo), "=f"(hi) : "l"(x[k]));
            // MUFU pipe: exp2; flushes huge-negative to 0 natively
            float e0 = ex2f(lo);
            float e1 = ex2f(hi);
            u64 pe = pk(e0, e1);
            ADD2(acc[k], pe, acc[k]);
        }
    }

#pragma unroll
    for (int k = 0; k < MPT; k++) {
        float v0 = __uint_as_float((unsigned)acc[k]);
        float v1 = __uint_as_float((unsigned)(acc[k] >> 32));
        g_part[b * MM + mbase + k * MT][ch] = v0 + v1;
    }
}

// ---------- reduction: 64 blocks x 256 thr; shuffle-based, 1 barrier -------
__global__ __launch_bounds__(RED_T) void gmm_red_kernel(float* __restrict__ out) {
    __shared__ float wsum[RED_T / 32];    // 8 per-warp sums
    __shared__ bool amLast;
    const int tid  = threadIdx.x;
    const int lane = tid & 31;
    const int wid  = tid >> 5;
    const int i = blockIdx.x * RED_T + tid;     // 0 .. BB*MM-1

    // 32 contiguous floats per m: 8 x LDG.128, MLP=8
    const float4* p = (const float4*)g_part[i];
    float s = 0.0f;
#pragma unroll
    for (int c = 0; c < NCHUNK / 4; c++) {
        float4 v = p[c];
        s += (v.x + v.y) + (v.z + v.w);
    }
    float nll = -__logf(s);                     // nll = -ln(sum e^lp)

    float w = warp_sum(nll);                    // 5 shfl, no barriers
    if (lane == 0) wsum[wid] = w;
    __syncthreads();                            // the only block barrier

    if (wid == 0) {
        float v = (lane < RED_T / 32) ? wsum[lane] : 0.0f;
#pragma unroll
        for (int o = 4; o > 0; o >>= 1)
            v += __shfl_xor_sync(0xFFFFFFFFu, v, o);
        if (lane == 0) {
            g_red[blockIdx.x] = v;
            __threadfence();
            amLast = (atomicAdd(&g_count, 1u) == RED_BLOCKS - 1);
        }
    }
    __syncthreads();
    if (!amLast) return;

    // final: one warp combines 64 block sums (fixed tree order, deterministic)
    if (wid == 0) {
        float v = g_red[lane] + g_red[lane + 32];
#pragma unroll
        for (int o = 16; o > 0; o >>= 1)
            v += __shfl_xor_sync(0xFFFFFFFFu, v, o);
        if (lane == 0) {
            out[0] = v * (1.0f / (BB * MM));
            g_count = 0;                        // reset for next graph replay
        }
    }
}

extern "C" void kernel_launch(void* const* d_in, const int* in_sizes, int n_in,
                              void* d_out, int out_size) {
    const float* pred_xyz   = (const float*)d_in[0];  // [B, N, 3]
    const float* pred_sigma = (const float*)d_in[1];  // [B, N, 2]
    const float* target     = (const float*)d_in[2];  // [B, M, 3]
    float* out = (float*)d_out;

    dim3 grid(MTILES, NCHUNK, BB);
    gmm_main_kernel<<<grid, MT>>>(pred_xyz, pred_sigma, target);

    gmm_red_kernel<<<RED_BLOCKS, RED_T>>>(out);
}